// round 15
// baseline (speedup 1.0000x reference)
#include <cuda_runtime.h>
#include <cuda_fp16.h>
#include <math.h>
#include <stdint.h>

#define BS 128
#define LATENT 512
#define HID 1024
#define G4 4096       // 4*HID
#define KTOT 1536     // LATENT + HID unified K
#define NBLK 128
#define NTHR_A 256    // phase-A threads (warps 0-7)
#define NTHR_T 320    // total threads (warps 8-9 = phase B)
#define NCHUNK 24     // KTOT / 64
#define CHK 64        // fp16 K elems per chunk (= 128 bytes/row)

// iteration -> K-chunk map: h-part (chunks 8..23) first, x-part (0..7) last
#define MAPC(c) ((c) < 16 ? (c) + 8 : (c) - 16)

typedef unsigned long long u64;
typedef unsigned int u32;

// ---------------- persistent device-global state (no runtime alloc) --------
__device__ __align__(16) __half g_W[2][G4][KTOT];       // weight, fp16, gate-interleaved
__device__ __align__(16) __half g_Ahi[2][2][BS][KTOT];  // [buf][dir][row][k] activation hi
__device__ __align__(16) __half g_Alo[2][2][BS][KTOT];  // activation lo (fp32 residual)
__device__ __align__(16) float g_bias[2][G4];           // gate-interleaved bias
__device__ __align__(16) float g_h[2][2][BS][HID];      // fp32 h for head [buf][dir]
__device__ __align__(16) float g_c[2][BS][HID];         // cell state [dir]
__device__ u64 g_harr;                                  // epilogue arrivals (h ready)
__device__ u64 g_xarrive;                               // phase-B arrivals (x ready)

// ---------------- helpers --------------------------------------------------
__device__ __forceinline__ void unpack2(u64 v, float& lo, float& hi) {
    asm("mov.b64 {%0, %1}, %2;" : "=f"(lo), "=f"(hi) : "l"(v));
}
__device__ __forceinline__ void fma2(u64& d, u64 a, u64 b) {
    asm("fma.rn.f32x2 %0, %1, %2, %0;" : "+l"(d) : "l"(a), "l"(b));
}
__device__ __forceinline__ u32 smem_u32(const void* p) {
    u32 a; asm("{ .reg .u64 t; cvta.to.shared.u64 t, %1; cvt.u32.u64 %0, t; }" : "=r"(a) : "l"(p));
    return a;
}

#define SW128(x) ((x) ^ (((x) >> 3) & 0x70))

#define CP16(dst, src) \
    asm volatile("cp.async.cg.shared.global [%0], [%1], 16;" :: "r"(dst), "l"(src))
#define CP_COMMIT() asm volatile("cp.async.commit_group;" ::: "memory")
#define CP_WAIT(n)  asm volatile("cp.async.wait_group %0;" :: "n"(n) : "memory")

#define BAR_A() asm volatile("bar.sync 1, 256;" ::: "memory")
#define BAR_B() asm volatile("bar.sync 2, 64;"  ::: "memory")

#define LDSM4(R, A)                                                          \
    asm volatile("ldmatrix.sync.aligned.m8n8.x4.shared.b16 {%0,%1,%2,%3}, [%4];" \
                 : "=r"((R)[0]), "=r"((R)[1]), "=r"((R)[2]), "=r"((R)[3])    \
                 : "r"(A))

#define MMA16816(D, A, B0, B1)                                               \
    asm volatile("mma.sync.aligned.m16n8k16.row.col.f32.f16.f16.f32 "        \
                 "{%0,%1,%2,%3}, {%4,%5,%6,%7}, {%8,%9}, {%0,%1,%2,%3};"     \
                 : "+f"((D)[0]), "+f"((D)[1]), "+f"((D)[2]), "+f"((D)[3])    \
                 : "r"((A)[0]), "r"((A)[1]), "r"((A)[2]), "r"((A)[3]),       \
                   "r"(B0), "r"(B1))

__device__ __forceinline__ void poll_counter(u64* addr, u64 target) {
    u64 v;
    do {
        asm volatile("ld.acquire.gpu.u64 %0, [%1];" : "=l"(v) : "l"(addr) : "memory");
    } while (v < target);
}
__device__ __forceinline__ void release_add(u64* addr) {
    u64 old;
    asm volatile("atom.add.release.gpu.u64 %0, [%1], 1;"
                 : "=l"(old) : "l"(addr) : "memory");
}

// fast nonlinearities (MUFU-based; rel err ~1e-6)
__device__ __forceinline__ float fast_sigmoid(float x) {
    return __fdividef(1.f, 1.f + __expf(-x));
}
__device__ __forceinline__ float fast_tanh(float x) {
    return 1.f - __fdividef(2.f, 1.f + __expf(2.f * x));
}

// smem: 3 stages of 40 KB (Ah 16K | Al 16K | W 8K) + 32 KB phase-B s_hb
#define STG    40960
#define OFF_AL 16384
#define OFF_W  32768
#define OFF_HB (3 * STG)
#define DYN_SMEM (3 * STG + 8 * HID * 4)

// ---------------------------------------------------------------------------
// prep (unchanged math): gate-interleave fp16 weights; split activations.
// ---------------------------------------------------------------------------
__global__ void prep_kernel(const float* __restrict__ Wih_f, const float* __restrict__ Whh_f,
                            const float* __restrict__ b_f,
                            const float* __restrict__ Wih_b, const float* __restrict__ Whh_b,
                            const float* __restrict__ b_b,
                            const float* __restrict__ dec) {
    int idx = blockIdx.x * blockDim.x + threadIdx.x;
    int stride = gridDim.x * blockDim.x;
    if (idx == 0) { g_harr = 0ULL; g_xarrive = 0ULL; }

    for (int i = idx; i < 2 * G4 * KTOT; i += stride) {
        int dir = i / (G4 * KTOT);
        int rem = i - dir * (G4 * KTOT);
        int r = rem / KTOT, k = rem - r * KTOT;
        int orow = (r & 3) * HID + (r >> 2);
        float w;
        if (k < LATENT) w = (dir ? Wih_b : Wih_f)[orow * LATENT + k];
        else            w = (dir ? Whh_b : Whh_f)[orow * HID + (k - LATENT)];
        g_W[dir][r][k] = __float2half_rn(w);
    }
    for (int i = idx; i < 2 * G4; i += stride) {
        int dir = i / G4, r = i - dir * G4;
        g_bias[dir][r] = (dir ? b_b : b_f)[(r & 3) * HID + (r >> 2)];
    }
    for (int i = idx; i < 2 * 2 * BS * KTOT; i += stride) {
        int buf = i / (2 * BS * KTOT);
        int rem = i - buf * (2 * BS * KTOT);
        int dir = rem / (BS * KTOT);
        int rem2 = rem - dir * (BS * KTOT);
        int row = rem2 / KTOT, k = rem2 - row * KTOT;
        float v = (buf == 0 && k < LATENT) ? dec[row * LATENT + k] : 0.f;
        __half hi = __float2half_rn(v);
        __half lo = __float2half_rn(v - __half2float(hi));
        g_Ahi[buf][dir][row][k] = hi;
        g_Alo[buf][dir][row][k] = lo;
    }
    for (int i = idx; i < 2 * 2 * BS * HID; i += stride) ((float*)g_h)[i] = 0.f;
    for (int i = idx; i < 2 * BS * HID; i += stride)     ((float*)g_c)[i] = 0.f;
}

// ---------------------------------------------------------------------------
// persistent kernel, warp-specialized:
//   warps 0-7 (256 thr): phase A GEMM + LSTM epilogue per step; bar.sync 1.
//   warps 8-9 (64 thr):  phase B (out[t-1], x(t)) per step; bar.sync 2.
// Cross-group sync only via monotonic counters g_harr / g_xarrive.
// ---------------------------------------------------------------------------
__global__ void __launch_bounds__(NTHR_T, 1) lstm_persist(
        int T, float* __restrict__ out,
        const float* __restrict__ W_out, const float* __restrict__ b_out,
        const float* __restrict__ W_fc1, const float* __restrict__ b_fc1) {

    extern __shared__ __align__(16) unsigned char dsm[];
    const u32 smem_base = smem_u32(dsm);

    const int tid = threadIdx.x;
    const int bid = blockIdx.x;

    // head mapping (shared by both groups)
    const int bt = bid >> 3;   // 16 row-tiles of 8
    const int lt = bid & 7;    // 8 latent col-tiles of 64
    float* s_hb = (float*)(dsm + OFF_HB);   // [8][1024] floats

    if (tid < NTHR_A) {
        // ================= phase A group (warps 0-7) =======================
        const int wid = tid >> 5;
        const int lane = tid & 31;
        const int dir = bid >> 6;
        const int colbase = (bid & 63) << 6;

        const int wm = wid & 3;
        const int wn = wid >> 2;
        const int R0 = wm * 32;
        const int C0 = wn * 32;

        const int arow = lane & 15;
        const u32 khA = (u32)(lane >> 4) * 16;
        const int brow = (lane & 7) + ((lane >> 4) & 1) * 8;
        const u32 khB = (u32)((lane >> 3) & 1) * 16;
        const u32 swA = (u32)(arow & 7) << 4;
        const u32 swB = (u32)(brow & 7) << 4;
        const u32 aRowOff0 = (u32)(R0 + arow) * 128;
        const u32 aRowOff1 = (u32)(R0 + 16 + arow) * 128;
        const u32 bRowOff0 = OFF_W + (u32)(C0 + brow) * 128;
        const u32 bRowOff1 = OFF_W + (u32)(C0 + 16 + brow) * 128;

        u32 cpdstA[4], cpdstW[2];
        int cprowA[4], cpqA[4], cprowW[2], cpqW[2];
#pragma unroll
        for (int i = 0; i < 4; i++) {
            int p = tid + i * NTHR_A, row = p >> 3, q = p & 7;
            cprowA[i] = row; cpqA[i] = q;
            cpdstA[i] = SW128((u32)(row * 128 + q * 16));
        }
#pragma unroll
        for (int i = 0; i < 2; i++) {
            int p = tid + i * NTHR_A, row = p >> 3, q = p & 7;
            cprowW[i] = row; cpqW[i] = q;
            cpdstW[i] = SW128((u32)(row * 128 + q * 16));
        }

        for (int t = 0; t < T; t++) {
            const int cur = t & 1;
            const int nxt = cur ^ 1;
            const __half* __restrict__ Ah = &g_Ahi[cur][dir][0][0];
            const __half* __restrict__ Al = &g_Alo[cur][dir][0][0];
            const __half* __restrict__ Wp = &g_W[dir][colbase][0];

#define ISSUE_CHUNK(cc, st)                                                   \
            {                                                                  \
                const u32 sb = smem_base + (u32)(st) * STG;                    \
                const size_t c64 = (size_t)(cc) * CHK;                         \
                _Pragma("unroll")                                              \
                for (int i = 0; i < 4; i++) {                                  \
                    const char* s  = (const char*)(Ah + (size_t)cprowA[i] * KTOT + c64) + cpqA[i] * 16; \
                    const char* s2 = (const char*)(Al + (size_t)cprowA[i] * KTOT + c64) + cpqA[i] * 16; \
                    CP16(sb + cpdstA[i], s);                                   \
                    CP16(sb + OFF_AL + cpdstA[i], s2);                         \
                }                                                              \
                _Pragma("unroll")                                              \
                for (int i = 0; i < 2; i++) {                                  \
                    const char* s = (const char*)(Wp + (size_t)cprowW[i] * KTOT + c64) + cpqW[i] * 16; \
                    CP16(sb + OFF_W + cpdstW[i], s);                           \
                }                                                              \
                CP_COMMIT();                                                   \
            }

            float acc[2][4][4];
#pragma unroll
            for (int mt = 0; mt < 2; mt++)
#pragma unroll
                for (int nt = 0; nt < 4; nt++)
#pragma unroll
                    for (int i = 0; i < 4; i++) acc[mt][nt][i] = 0.f;

            // h(t) full (all epilogues of step t-1)
            if (tid == 0) poll_counter(&g_harr, (u64)t * NBLK);
            BAR_A();
            ISSUE_CHUNK(MAPC(0), 0);

            int stage = 0;
#pragma unroll 1
            for (int c = 0; c < NCHUNK; c++) {
                if (c + 1 < NCHUNK) {
                    if (c + 1 == 16) {
                        // x(t) ready (all phase-B iterations t2 == t)
                        if (tid == 0) poll_counter(&g_xarrive, (u64)t * NBLK);
                        BAR_A();
                    }
                    const int nstage = (stage == 2) ? 0 : stage + 1;
                    ISSUE_CHUNK(MAPC(c + 1), nstage);
                    CP_WAIT(1);
                } else {
                    CP_WAIT(0);
                }
                BAR_A();   // chunk c visible; ring period 3 protects reuse

                const u32 sb = smem_base + (u32)stage * STG;
                const u32 a0 = sb + aRowOff0, a1 = sb + aRowOff1;
                const u32 b0 = sb + bRowOff0, b1 = sb + bRowOff1;

#pragma unroll
                for (int kk = 0; kk < 4; kk++) {
                    const u32 xA = ((u32)(kk * 32) + khA) ^ swA;
                    const u32 xB = ((u32)(kk * 32) + khB) ^ swB;
                    u32 ah[2][4], al[2][4], bw[2][4];
                    LDSM4(ah[0], a0 + xA);
                    LDSM4(ah[1], a1 + xA);
                    LDSM4(al[0], a0 + OFF_AL + xA);
                    LDSM4(al[1], a1 + OFF_AL + xA);
                    LDSM4(bw[0], b0 + xB);
                    LDSM4(bw[1], b1 + xB);
#pragma unroll
                    for (int mt = 0; mt < 2; mt++)
#pragma unroll
                        for (int np = 0; np < 2; np++)
#pragma unroll
                            for (int hf = 0; hf < 2; hf++) {
                                const int nt = np * 2 + hf;
                                MMA16816(acc[mt][nt], ah[mt], bw[np][2 * hf], bw[np][2 * hf + 1]);
                                MMA16816(acc[mt][nt], al[mt], bw[np][2 * hf], bw[np][2 * hf + 1]);
                            }
                }
                stage = (stage == 2) ? 0 : stage + 1;
            }

            // ---- epilogue: pair-exchange quads, LSTM cell, write h(t+1) ----
#pragma unroll
            for (int mt = 0; mt < 2; mt++)
#pragma unroll
                for (int nt = 0; nt < 4; nt++) {
                    float d0 = acc[mt][nt][0], d1 = acc[mt][nt][1];
                    float d2 = acc[mt][nt][2], d3 = acc[mt][nt][3];
                    float p0 = __shfl_xor_sync(0xffffffffu, d0, 1);
                    float p1 = __shfl_xor_sync(0xffffffffu, d1, 1);
                    float p2 = __shfl_xor_sync(0xffffffffu, d2, 1);
                    float p3 = __shfl_xor_sync(0xffffffffu, d3, 1);
                    if (!(lane & 1)) {
                        const int q = (lane >> 1) & 1;
                        const int col4 = colbase + C0 + nt * 8 + q * 4;
                        const int jp = col4 >> 2;
                        const float4 b4 = *(const float4*)&g_bias[dir][col4];
                        const int r0 = R0 + mt * 16 + (lane >> 2);
#pragma unroll
                        for (int rr = 0; rr < 2; rr++) {
                            const int row = r0 + rr * 8;
                            float zi = (rr ? d2 : d0) + b4.x;
                            float zf = (rr ? d3 : d1) + b4.y;
                            float zg = (rr ? p2 : p0) + b4.z;
                            float zo = (rr ? p3 : p1) + b4.w;
                            float si = fast_sigmoid(zi);
                            float sf = fast_sigmoid(zf);
                            float so = fast_sigmoid(zo);
                            float c2 = sf * g_c[dir][row][jp] + si * fast_tanh(zg);
                            g_c[dir][row][jp] = c2;
                            float hv = so * fast_tanh(c2);
                            g_h[nxt][dir][row][jp] = hv;
                            __half hhi = __float2half_rn(hv);
                            __half hlo = __float2half_rn(hv - __half2float(hhi));
                            g_Ahi[nxt][dir][row][LATENT + jp] = hhi;
                            g_Alo[nxt][dir][row][LATENT + jp] = hlo;
                        }
                    }
                }

            BAR_A();                       // all h writes done group-wide
            if (tid == 0) release_add(&g_harr);
        }
    } else {
        // ================= phase B group (warps 8-9, 64 threads) ===========
        const int btid = tid - NTHR_A;     // 0..63
        const int l = lt * 64 + btid;      // this thread's latent column

        for (int t2 = 1; t2 <= T; t2++) {
            const int hbuf = t2 & 1;       // buffer holding h(t2)

            // wait h(t2) full; BAR_B also orders prev iter's s_hb reads
            if (btid == 0) poll_counter(&g_harr, (u64)t2 * NBLK);
            BAR_B();

            // stage hb rows bt*8..+7 into smem (L2-direct source)
            for (int i = btid; i < 8 * 256; i += 64) {
                int r = i >> 8;
                int k = (i & 255) * 4;
                *(float4*)&s_hb[r * HID + k] =
                    __ldcg((const float4*)&g_h[hbuf][1][bt * 8 + r][k]);
            }
            BAR_B();

            // x(t2) = hb @ W_out^T + b_out, split fp16 hi/lo, both dirs
            {
                const ulonglong2* __restrict__ wp2 =
                    (const ulonglong2*)(W_out + (size_t)l * HID);
                const ulonglong2* __restrict__ hp2 = (const ulonglong2*)s_hb;
                u64 hacc[8];
#pragma unroll
                for (int r = 0; r < 8; r++) hacc[r] = 0ull;
#pragma unroll 2
                for (int k4 = 0; k4 < 256; k4++) {
                    ulonglong2 ww = wp2[k4];
#pragma unroll
                    for (int r = 0; r < 8; r++) {
                        ulonglong2 hh = hp2[r * 256 + k4];
                        fma2(hacc[r], ww.x, hh.x);
                        fma2(hacc[r], ww.y, hh.y);
                    }
                }
                const float bo = b_out[l];
#pragma unroll
                for (int r = 0; r < 8; r++) {
                    float lo, hi; unpack2(hacc[r], lo, hi);
                    float xv = lo + hi + bo;
                    int row = bt * 8 + r;
                    __half xh = __float2half_rn(xv);
                    __half xl = __float2half_rn(xv - __half2float(xh));
                    g_Ahi[hbuf][0][row][l] = xh;
                    g_Ahi[hbuf][1][row][l] = xh;
                    g_Alo[hbuf][0][row][l] = xl;
                    g_Alo[hbuf][1][row][l] = xl;
                }
            }

            // out[b, t2-1] = relu(concat(hf,hb)) . W_fc1 + b_fc1  (lt==0)
            if (lt == 0) {
                const int r = btid >> 3;          // 0..7
                const int ln = btid & 7;          // 0..7
                const int b = bt * 8 + r;
                const float* __restrict__ hf = &g_h[hbuf][0][b][0];
                float facc = 0.f;
                for (int k = ln * 4; k < HID; k += 32) {
                    float4 f   = __ldcg((const float4*)&hf[k]);
                    float4 wf  = *(const float4*)&W_fc1[k];
                    float4 hb4 = *(const float4*)&s_hb[r * HID + k];
                    float4 wb  = *(const float4*)&W_fc1[HID + k];
                    facc += fmaxf(f.x, 0.f) * wf.x + fmaxf(f.y, 0.f) * wf.y
                          + fmaxf(f.z, 0.f) * wf.z + fmaxf(f.w, 0.f) * wf.w
                          + fmaxf(hb4.x, 0.f) * wb.x + fmaxf(hb4.y, 0.f) * wb.y
                          + fmaxf(hb4.z, 0.f) * wb.z + fmaxf(hb4.w, 0.f) * wb.w;
                }
#pragma unroll
                for (int off = 4; off; off >>= 1)
                    facc += __shfl_xor_sync(0xffffffffu, facc, off);
                if (ln == 0) out[(size_t)b * T + (t2 - 1)] = facc + b_fc1[0];
            }

            BAR_B();                       // x writes + s_hb reads complete
            if (btid == 0) release_add(&g_xarrive);
        }
    }
}

// ---------------------------------------------------------------------------
extern "C" void kernel_launch(void* const* d_in, const int* in_sizes, int n_in,
                              void* d_out, int out_size) {
    const float* dec   = (const float*)d_in[0];
    // d_in[1] = lengths (T derives from out_size)
    const float* Wih_f = (const float*)d_in[2];
    const float* Whh_f = (const float*)d_in[3];
    const float* b_f   = (const float*)d_in[4];
    const float* Wih_b = (const float*)d_in[5];
    const float* Whh_b = (const float*)d_in[6];
    const float* b_b   = (const float*)d_in[7];
    const float* W_out = (const float*)d_in[8];
    const float* b_out = (const float*)d_in[9];
    const float* W_fc1 = (const float*)d_in[10];
    const float* b_fc1 = (const float*)d_in[11];
    float* out = (float*)d_out;

    const int T = out_size / BS;

    cudaFuncSetAttribute(lstm_persist, cudaFuncAttributeMaxDynamicSharedMemorySize, DYN_SMEM);

    prep_kernel<<<1024, 256>>>(Wih_f, Whh_f, b_f, Wih_b, Whh_b, b_b, dec);
    if (T > 0) {
        lstm_persist<<<NBLK, NTHR_T, DYN_SMEM>>>(T, out, W_out, b_out, W_fc1, b_fc1);
    }
}

// round 16
// speedup vs baseline: 1.1479x; 1.1479x over previous
#include <cuda_runtime.h>
#include <cuda_fp16.h>
#include <math.h>
#include <stdint.h>

#define BS 128
#define LATENT 512
#define HID 1024
#define G4 4096       // 4*HID
#define KTOT 1536     // LATENT + HID unified K
#define NBLK 128
#define NTHR 256
#define NCHUNK 12     // KTOT / 128
#define CHK 128       // fp16 K elems per chunk (= 256 bytes/row, 2 SW128 subtiles)

// iteration -> K-chunk map: h-part (chunks 4..11) first, x-part (0..3) last
#define MAPC(c) ((c) < 8 ? (c) + 4 : (c) - 8)

// phase-B padded s_hb layout: 4 segments of 260 floats per row (256 used)
#define SEGF 260
#define ROWF (4 * SEGF)   // 1040 floats per row

typedef unsigned long long u64;
typedef unsigned int u32;

// ---------------- persistent device-global state (no runtime alloc) --------
__device__ __align__(16) __half g_W[2][G4][KTOT];       // weight, fp16, gate-interleaved
__device__ __align__(16) __half g_Ahi[2][2][BS][KTOT];  // [buf][dir][row][k] activation hi
__device__ __align__(16) __half g_Alo[2][2][BS][KTOT];  // activation lo (fp32 residual)
__device__ __align__(16) float g_bias[2][G4];           // gate-interleaved bias
__device__ __align__(16) float g_h[2][2][BS][HID];      // fp32 h for head [buf][dir]
__device__ __align__(16) float g_c[2][BS][HID];         // cell state [dir]
__device__ u64 g_arrive;                                // grid barrier counter (h ready)
__device__ u64 g_xarrive;                               // producer flag (x_next ready)

// ---------------- helpers --------------------------------------------------
__device__ __forceinline__ void unpack2(u64 v, float& lo, float& hi) {
    asm("mov.b64 {%0, %1}, %2;" : "=f"(lo), "=f"(hi) : "l"(v));
}
__device__ __forceinline__ void fma2(u64& d, u64 a, u64 b) {
    asm("fma.rn.f32x2 %0, %1, %2, %0;" : "+l"(d) : "l"(a), "l"(b));
}
__device__ __forceinline__ u32 smem_u32(const void* p) {
    u32 a; asm("{ .reg .u64 t; cvta.to.shared.u64 t, %1; cvt.u32.u64 %0, t; }" : "=r"(a) : "l"(p));
    return a;
}

#define SW128(x) ((x) ^ (((x) >> 3) & 0x70))

#define CP16(dst, src) \
    asm volatile("cp.async.cg.shared.global [%0], [%1], 16;" :: "r"(dst), "l"(src))
#define CP_COMMIT() asm volatile("cp.async.commit_group;" ::: "memory")
#define CP_WAIT(n)  asm volatile("cp.async.wait_group %0;" :: "n"(n) : "memory")

#define LDSM4(R, A)                                                          \
    asm volatile("ldmatrix.sync.aligned.m8n8.x4.shared.b16 {%0,%1,%2,%3}, [%4];" \
                 : "=r"((R)[0]), "=r"((R)[1]), "=r"((R)[2]), "=r"((R)[3])    \
                 : "r"(A))

#define MMA16816(D, A, B0, B1)                                               \
    asm volatile("mma.sync.aligned.m16n8k16.row.col.f32.f16.f16.f32 "        \
                 "{%0,%1,%2,%3}, {%4,%5,%6,%7}, {%8,%9}, {%0,%1,%2,%3};"     \
                 : "+f"((D)[0]), "+f"((D)[1]), "+f"((D)[2]), "+f"((D)[3])    \
                 : "r"((A)[0]), "r"((A)[1]), "r"((A)[2]), "r"((A)[3]),       \
                   "r"(B0), "r"(B1))

// Fence-free grid barrier (h visibility). Release via atom.add.release.gpu;
// acquire via leader ld.acquire.gpu poll. No CCTL.IVALL: all cross-block
// reads bypass L1 (cp.async.cg / __ldcg).
__device__ __forceinline__ void grid_sync(u64 target) {
    __syncthreads();
    if (threadIdx.x == 0) {
        u64 old;
        asm volatile("atom.add.release.gpu.u64 %0, [%1], 1;"
                     : "=l"(old) : "l"(&g_arrive) : "memory");
        u64 v;
        do {
            asm volatile("ld.acquire.gpu.u64 %0, [%1];"
                         : "=l"(v) : "l"(&g_arrive) : "memory");
        } while (v < target);
    }
    __syncthreads();
}

// fast nonlinearities (MUFU-based; rel err ~1e-6)
__device__ __forceinline__ float fast_sigmoid(float x) {
    return __fdividef(1.f, 1.f + __expf(-x));
}
__device__ __forceinline__ float fast_tanh(float x) {
    return 1.f - __fdividef(2.f, 1.f + __expf(2.f * x));
}

// smem: 2 stages of 80 KB. Stage layout: Ah 32K | Al 32K | W 16K.
// Each tile stored as two 128B-pitch SW128 subtiles (k-halves of 64 elems).
#define STG    81920
#define OFF_AL 32768
#define OFF_W  65536
#define DYN_SMEM (2 * STG)   // 160 KB; s_hb (33 KB) aliases stage 0

// ---------------------------------------------------------------------------
// prep (unchanged math): gate-interleave fp16 weights; split activations.
// ---------------------------------------------------------------------------
__global__ void prep_kernel(const float* __restrict__ Wih_f, const float* __restrict__ Whh_f,
                            const float* __restrict__ b_f,
                            const float* __restrict__ Wih_b, const float* __restrict__ Whh_b,
                            const float* __restrict__ b_b,
                            const float* __restrict__ dec) {
    int idx = blockIdx.x * blockDim.x + threadIdx.x;
    int stride = gridDim.x * blockDim.x;
    if (idx == 0) { g_arrive = 0ULL; g_xarrive = 0ULL; }

    for (int i = idx; i < 2 * G4 * KTOT; i += stride) {
        int dir = i / (G4 * KTOT);
        int rem = i - dir * (G4 * KTOT);
        int r = rem / KTOT, k = rem - r * KTOT;
        int orow = (r & 3) * HID + (r >> 2);
        float w;
        if (k < LATENT) w = (dir ? Wih_b : Wih_f)[orow * LATENT + k];
        else            w = (dir ? Whh_b : Whh_f)[orow * HID + (k - LATENT)];
        g_W[dir][r][k] = __float2half_rn(w);
    }
    for (int i = idx; i < 2 * G4; i += stride) {
        int dir = i / G4, r = i - dir * G4;
        g_bias[dir][r] = (dir ? b_b : b_f)[(r & 3) * HID + (r >> 2)];
    }
    for (int i = idx; i < 2 * 2 * BS * KTOT; i += stride) {
        int buf = i / (2 * BS * KTOT);
        int rem = i - buf * (2 * BS * KTOT);
        int dir = rem / (BS * KTOT);
        int rem2 = rem - dir * (BS * KTOT);
        int row = rem2 / KTOT, k = rem2 - row * KTOT;
        float v = (buf == 0 && k < LATENT) ? dec[row * LATENT + k] : 0.f;
        __half hi = __float2half_rn(v);
        __half lo = __float2half_rn(v - __half2float(hi));
        g_Ahi[buf][dir][row][k] = hi;
        g_Alo[buf][dir][row][k] = lo;
    }
    for (int i = idx; i < 2 * 2 * BS * HID; i += stride) ((float*)g_h)[i] = 0.f;
    for (int i = idx; i < 2 * BS * HID; i += stride)     ((float*)g_c)[i] = 0.f;
}

// ---------------------------------------------------------------------------
// persistent kernel: 128 blocks x 256 threads, one launch for all T steps.
// phase A: block = (dir, 64 gate-cols); 4x2 warp grid, warp tile 32(M)x32(N).
//          fp16 2-term split mma.sync; cp.async 2-stage ring, CHK=128.
// phase B: after grid_sync, overlapped with next step's phase A via g_xarrive.
// ---------------------------------------------------------------------------
__global__ void __launch_bounds__(NTHR, 1) lstm_persist(
        int T, float* __restrict__ out,
        const float* __restrict__ W_out, const float* __restrict__ b_out,
        const float* __restrict__ W_fc1, const float* __restrict__ b_fc1) {

    extern __shared__ __align__(16) unsigned char dsm[];
    const u32 smem_base = smem_u32(dsm);

    const int tid = threadIdx.x;
    const int bid = blockIdx.x;
    const int wid = tid >> 5;
    const int lane = tid & 31;

    const int dir = bid >> 6;
    const int colbase = (bid & 63) << 6;

    // warp tile mapping: 4 warps along M (32 rows), 2 along N (32 cols)
    const int wm = wid & 3;
    const int wn = wid >> 2;
    const int R0 = wm * 32;
    const int C0 = wn * 32;

    // ldmatrix per-lane constants
    const int arow = lane & 15;
    const u32 khA = (u32)(lane >> 4) * 16;
    const int brow = (lane & 7) + ((lane >> 4) & 1) * 8;
    const u32 khB = (u32)((lane >> 3) & 1) * 16;
    const u32 swA = (u32)(arow & 7) << 4;
    const u32 swB = (u32)(brow & 7) << 4;
    const u32 aRowOff0 = (u32)(R0 + arow) * 128;
    const u32 aRowOff1 = (u32)(R0 + 16 + arow) * 128;
    const u32 bRowOff0 = OFF_W + (u32)(C0 + brow) * 128;
    const u32 bRowOff1 = OFF_W + (u32)(C0 + 16 + brow) * 128;

    // cp.async per-thread precompute. Row pitch 256B = two 128B SW128 subtiles.
    // A (32 KB = 2048 x 16B): 8 per thread. W (16 KB = 1024 x 16B): 4 per thread.
    u32 cpdstA[8], cpdstW[4];
    int cprowA[8], cpqA[8], cprowW[4], cpqW[4];
#pragma unroll
    for (int i = 0; i < 8; i++) {
        int p = tid + i * NTHR;          // 0..2047
        int row = p >> 4, q = p & 15;    // q: 16B unit within 256B row
        cprowA[i] = row; cpqA[i] = q;
        cpdstA[i] = (u32)((q >> 3) * 16384) + SW128((u32)(row * 128 + (q & 7) * 16));
    }
#pragma unroll
    for (int i = 0; i < 4; i++) {
        int p = tid + i * NTHR;          // 0..1023
        int row = p >> 4, q = p & 15;
        cprowW[i] = row; cpqW[i] = q;
        cpdstW[i] = (u32)((q >> 3) * 8192) + SW128((u32)(row * 128 + (q & 7) * 16));
    }

    // head mapping
    const int bt = bid >> 3;   // 16 row-tiles of 8
    const int lt = bid & 7;    // 8 latent col-tiles of 64
    float* s_hb_f = (float*)dsm;   // segmented layout, aliases stage 0

    for (int t = 0; t < T; t++) {
        const int cur = t & 1;
        const int nxt = cur ^ 1;
        const __half* __restrict__ Ah = &g_Ahi[cur][dir][0][0];
        const __half* __restrict__ Al = &g_Alo[cur][dir][0][0];
        const __half* __restrict__ Wp = &g_W[dir][colbase][0];
        const u64 xtarget = (u64)t * NBLK;   // phase B(t-1) arrivals gate x(t)

#define ISSUE_CHUNK(cc, st)                                                   \
        {                                                                      \
            const u32 sb = smem_base + (u32)(st) * STG;                        \
            const size_t c128 = (size_t)(cc) * CHK;                            \
            _Pragma("unroll")                                                  \
            for (int i = 0; i < 8; i++) {                                      \
                const __half* s  = Ah + (size_t)cprowA[i] * KTOT + c128 + cpqA[i] * 8; \
                const __half* s2 = Al + (size_t)cprowA[i] * KTOT + c128 + cpqA[i] * 8; \
                CP16(sb + cpdstA[i], s);                                       \
                CP16(sb + OFF_AL + cpdstA[i], s2);                             \
            }                                                                  \
            _Pragma("unroll")                                                  \
            for (int i = 0; i < 4; i++) {                                      \
                const __half* s = Wp + (size_t)cprowW[i] * KTOT + c128 + cpqW[i] * 8; \
                CP16(sb + OFF_W + cpdstW[i], s);                               \
            }                                                                  \
            CP_COMMIT();                                                       \
        }

        // ================= phase A: fp16 2-term HMMA, 12 chunks ============
        float acc[2][4][4];
#pragma unroll
        for (int mt = 0; mt < 2; mt++)
#pragma unroll
            for (int nt = 0; nt < 4; nt++)
#pragma unroll
                for (int i = 0; i < 4; i++) acc[mt][nt][i] = 0.f;

        ISSUE_CHUNK(MAPC(0), 0);   // first h-chunk (no x dependency)

#pragma unroll 1
        for (int c = 0; c < NCHUNK; c++) {
            const int stage = c & 1;
            CP_WAIT(0);              // chunk c complete (in flight a full MMA run)
            __syncthreads();         // visible to all; prev stage reads done

            if (c + 1 < NCHUNK) {
                if (c + 1 == 8) {
                    // about to issue first x-chunk: wait for all phase B(t-1)
                    if (tid == 0) {
                        u64 v;
                        do {
                            asm volatile("ld.acquire.gpu.u64 %0, [%1];"
                                         : "=l"(v) : "l"(&g_xarrive) : "memory");
                        } while (v < xtarget);
                    }
                    __syncthreads();
                }
                ISSUE_CHUNK(MAPC(c + 1), stage ^ 1);   // overlaps MMA below
            }

            const u32 sb = smem_base + (u32)stage * STG;
            const u32 a0 = sb + aRowOff0, a1 = sb + aRowOff1;
            const u32 b0 = sb + bRowOff0, b1 = sb + bRowOff1;

#pragma unroll
            for (int kk = 0; kk < 8; kk++) {
                const u32 shA = (u32)(kk >> 2) * 16384;
                const u32 shB = (u32)(kk >> 2) * 8192;
                const u32 xA = shA + ((((u32)(kk & 3)) * 32 + khA) ^ swA);
                const u32 xB = shB + ((((u32)(kk & 3)) * 32 + khB) ^ swB);
                u32 ah[2][4], al[2][4], bw[2][4];
                LDSM4(ah[0], a0 + xA);
                LDSM4(ah[1], a1 + xA);
                LDSM4(al[0], a0 + OFF_AL + xA);
                LDSM4(al[1], a1 + OFF_AL + xA);
                LDSM4(bw[0], b0 + xB);
                LDSM4(bw[1], b1 + xB);
#pragma unroll
                for (int mt = 0; mt < 2; mt++)
#pragma unroll
                    for (int np = 0; np < 2; np++)
#pragma unroll
                        for (int hf = 0; hf < 2; hf++) {
                            const int nt = np * 2 + hf;
                            MMA16816(acc[mt][nt], ah[mt], bw[np][2 * hf], bw[np][2 * hf + 1]);
                            MMA16816(acc[mt][nt], al[mt], bw[np][2 * hf], bw[np][2 * hf + 1]);
                        }
            }
        }

        // -------- epilogue: pair-exchange quads, LSTM cell, write h --------
#pragma unroll
        for (int mt = 0; mt < 2; mt++)
#pragma unroll
            for (int nt = 0; nt < 4; nt++) {
                float d0 = acc[mt][nt][0], d1 = acc[mt][nt][1];
                float d2 = acc[mt][nt][2], d3 = acc[mt][nt][3];
                float p0 = __shfl_xor_sync(0xffffffffu, d0, 1);
                float p1 = __shfl_xor_sync(0xffffffffu, d1, 1);
                float p2 = __shfl_xor_sync(0xffffffffu, d2, 1);
                float p3 = __shfl_xor_sync(0xffffffffu, d3, 1);
                if (!(lane & 1)) {
                    const int q = (lane >> 1) & 1;
                    const int col4 = colbase + C0 + nt * 8 + q * 4;
                    const int jp = col4 >> 2;
                    const float4 b4 = *(const float4*)&g_bias[dir][col4];
                    const int r0 = R0 + mt * 16 + (lane >> 2);
#pragma unroll
                    for (int rr = 0; rr < 2; rr++) {
                        const int row = r0 + rr * 8;
                        float zi = (rr ? d2 : d0) + b4.x;
                        float zf = (rr ? d3 : d1) + b4.y;
                        float zg = (rr ? p2 : p0) + b4.z;
                        float zo = (rr ? p3 : p1) + b4.w;
                        float si = fast_sigmoid(zi);
                        float sf = fast_sigmoid(zf);
                        float so = fast_sigmoid(zo);
                        float c2 = sf * g_c[dir][row][jp] + si * fast_tanh(zg);
                        g_c[dir][row][jp] = c2;
                        float hv = so * fast_tanh(c2);
                        g_h[nxt][dir][row][jp] = hv;
                        __half hhi = __float2half_rn(hv);
                        __half hlo = __float2half_rn(hv - __half2float(hhi));
                        g_Ahi[nxt][dir][row][LATENT + jp] = hhi;
                        g_Alo[nxt][dir][row][LATENT + jp] = hlo;
                    }
                }
            }

        grid_sync((u64)(t + 1) * NBLK);   // h(t) globally visible

        // ================= phase B: head (overlapped with next phase A) ====
        for (int i = tid; i < 8 * 256; i += NTHR) {
            int r = i >> 8;               // 0..7
            int k = (i & 255) * 4;        // 0..1020
            float4 v = __ldcg((const float4*)&g_h[nxt][1][bt * 8 + r][k]);
            *(float4*)&s_hb_f[r * ROWF + (k >> 8) * SEGF + (k & 255)] = v;
        }
        __syncthreads();

        // x_next = hb @ W_out^T + b_out, split to fp16 hi/lo for both dirs
        {
            const int l_loc = tid >> 2;
            const int q = tid & 3;
            const int l = lt * 64 + l_loc;
            const ulonglong2* __restrict__ wp2 =
                (const ulonglong2*)(W_out + (size_t)l * HID) + q * 64;
            const u64* __restrict__ hp = (const u64*)s_hb_f + q * (SEGF / 2);
            u64 hacc[8];
#pragma unroll
            for (int r = 0; r < 8; r++) hacc[r] = 0ull;
#pragma unroll 2
            for (int k4 = 0; k4 < 64; k4++) {
                ulonglong2 ww = wp2[k4];
#pragma unroll
                for (int r = 0; r < 8; r++) {
                    fma2(hacc[r], ww.x, hp[r * (ROWF / 2) + 2 * k4]);
                    fma2(hacc[r], ww.y, hp[r * (ROWF / 2) + 2 * k4 + 1]);
                }
            }
#pragma unroll
            for (int r = 0; r < 8; r++) {
                float lo, hi; unpack2(hacc[r], lo, hi);
                float s = lo + hi;
                s += __shfl_xor_sync(0xffffffffu, s, 1);
                s += __shfl_xor_sync(0xffffffffu, s, 2);
                if (q == 0) {
                    float xv = s + b_out[l];
                    int row = bt * 8 + r;
                    __half xh = __float2half_rn(xv);
                    __half xl = __float2half_rn(xv - __half2float(xh));
                    g_Ahi[nxt][0][row][l] = xh;
                    g_Ahi[nxt][1][row][l] = xh;
                    g_Alo[nxt][0][row][l] = xl;
                    g_Alo[nxt][1][row][l] = xl;
                }
            }
        }

        // out[b, t] = relu(concat(hf,hb)) . W_fc1 + b_fc1   (lt==0 blocks)
        if (lt == 0) {
            const int r = tid >> 5, ln = tid & 31;
            const int b = bt * 8 + r;
            const float* __restrict__ hf = &g_h[nxt][0][b][0];
            float facc = 0.f;
            for (int k = ln * 4; k < HID; k += 128) {
                float4 f   = __ldcg((const float4*)&hf[k]);
                float4 wf  = *(const float4*)&W_fc1[k];
                float4 hb4 = *(const float4*)&s_hb_f[r * ROWF + (k >> 8) * SEGF + (k & 255)];
                float4 wb  = *(const float4*)&W_fc1[HID + k];
                facc += fmaxf(f.x, 0.f) * wf.x + fmaxf(f.y, 0.f) * wf.y
                      + fmaxf(f.z, 0.f) * wf.z + fmaxf(f.w, 0.f) * wf.w
                      + fmaxf(hb4.x, 0.f) * wb.x + fmaxf(hb4.y, 0.f) * wb.y
                      + fmaxf(hb4.z, 0.f) * wb.z + fmaxf(hb4.w, 0.f) * wb.w;
            }
#pragma unroll
            for (int off = 16; off; off >>= 1)
                facc += __shfl_xor_sync(0xffffffffu, facc, off);
            if (ln == 0) out[(size_t)b * T + t] = facc + b_fc1[0];
        }

        // block-local completion of phase B (s_hb reads done before next
        // step's cp.async overwrites stage 0); then announce x(t+1) ready.
        __syncthreads();
        if (tid == 0) {
            u64 old;
            asm volatile("atom.add.release.gpu.u64 %0, [%1], 1;"
                         : "=l"(old) : "l"(&g_xarrive) : "memory");
        }
    }
}

// ---------------------------------------------------------------------------
extern "C" void kernel_launch(void* const* d_in, const int* in_sizes, int n_in,
                              void* d_out, int out_size) {
    const float* dec   = (const float*)d_in[0];
    // d_in[1] = lengths (T derives from out_size)
    const float* Wih_f = (const float*)d_in[2];
    const float* Whh_f = (const float*)d_in[3];
    const float* b_f   = (const float*)d_in[4];
    const float* Wih_b = (const float*)d_in[5];
    const float* Whh_b = (const float*)d_in[6];
    const float* b_b   = (const float*)d_in[7];
    const float* W_out = (const float*)d_in[8];
    const float* b_out = (const float*)d_in[9];
    const float* W_fc1 = (const float*)d_in[10];
    const float* b_fc1 = (const float*)d_in[11];
    float* out = (float*)d_out;

    const int T = out_size / BS;

    cudaFuncSetAttribute(lstm_persist, cudaFuncAttributeMaxDynamicSharedMemorySize, DYN_SMEM);

    prep_kernel<<<1024, 256>>>(Wih_f, Whh_f, b_f, Wih_b, Whh_b, b_b, dec);
    if (T > 0) {
        lstm_persist<<<NBLK, NTHR, DYN_SMEM>>>(T, out, W_out, b_out, W_fc1, b_fc1);
    }
}

// round 17
// speedup vs baseline: 1.1759x; 1.0244x over previous
#include <cuda_runtime.h>
#include <cuda_fp16.h>
#include <math.h>
#include <stdint.h>

#define BS 128
#define LATENT 512
#define HID 1024
#define G4 4096       // 4*HID
#define KTOT 1536     // LATENT + HID unified K
#define NBLK 128
#define NTHR 512      // 16 warps: group 0 = warps 0-7 (kk 0,1), group 1 = warps 8-15 (kk 2,3)
#define NCHUNK 24     // KTOT / 64
#define CHK 64        // fp16 K elems per chunk (= 128 bytes/row)

// iteration -> K-chunk map: h-part (chunks 8..23) first, x-part (0..7) last
#define MAPC(c) ((c) < 16 ? (c) + 8 : (c) - 16)

// phase-B padded s_hb layout: 8 segments of 132 floats per row (128 used)
#define SEGF 132
#define ROWF (8 * SEGF)   // 1056 floats per row

typedef unsigned long long u64;
typedef unsigned int u32;

// ---------------- persistent device-global state (no runtime alloc) --------
__device__ __align__(16) __half g_W[2][G4][KTOT];       // weight, fp16, gate-interleaved
__device__ __align__(16) __half g_Ahi[2][2][BS][KTOT];  // [buf][dir][row][k] activation hi
__device__ __align__(16) __half g_Alo[2][2][BS][KTOT];  // activation lo (fp32 residual)
__device__ __align__(16) float g_bias[2][G4];           // gate-interleaved bias
__device__ __align__(16) float g_h[2][2][BS][HID];      // fp32 h for head [buf][dir]
__device__ __align__(16) float g_c[2][BS][HID];         // cell state [dir]
__device__ u64 g_arrive;                                // grid barrier counter (h ready)
__device__ u64 g_xarrive;                               // producer flag (x_next ready)

// ---------------- helpers --------------------------------------------------
__device__ __forceinline__ void unpack2(u64 v, float& lo, float& hi) {
    asm("mov.b64 {%0, %1}, %2;" : "=f"(lo), "=f"(hi) : "l"(v));
}
__device__ __forceinline__ void fma2(u64& d, u64 a, u64 b) {
    asm("fma.rn.f32x2 %0, %1, %2, %0;" : "+l"(d) : "l"(a), "l"(b));
}
__device__ __forceinline__ u32 smem_u32(const void* p) {
    u32 a; asm("{ .reg .u64 t; cvta.to.shared.u64 t, %1; cvt.u32.u64 %0, t; }" : "=r"(a) : "l"(p));
    return a;
}

#define SW128(x) ((x) ^ (((x) >> 3) & 0x70))

#define CP16(dst, src) \
    asm volatile("cp.async.cg.shared.global [%0], [%1], 16;" :: "r"(dst), "l"(src))
#define CP_COMMIT() asm volatile("cp.async.commit_group;" ::: "memory")
#define CP_WAIT(n)  asm volatile("cp.async.wait_group %0;" :: "n"(n) : "memory")

#define LDSM4(R, A)                                                          \
    asm volatile("ldmatrix.sync.aligned.m8n8.x4.shared.b16 {%0,%1,%2,%3}, [%4];" \
                 : "=r"((R)[0]), "=r"((R)[1]), "=r"((R)[2]), "=r"((R)[3])    \
                 : "r"(A))

#define MMA16816(D, A, B0, B1)                                               \
    asm volatile("mma.sync.aligned.m16n8k16.row.col.f32.f16.f16.f32 "        \
                 "{%0,%1,%2,%3}, {%4,%5,%6,%7}, {%8,%9}, {%0,%1,%2,%3};"     \
                 : "+f"((D)[0]), "+f"((D)[1]), "+f"((D)[2]), "+f"((D)[3])    \
                 : "r"((A)[0]), "r"((A)[1]), "r"((A)[2]), "r"((A)[3]),       \
                   "r"(B0), "r"(B1))

// Fence-free grid barrier (h visibility). Release via atom.add.release.gpu;
// acquire via leader ld.acquire.gpu poll. No CCTL.IVALL: all cross-block
// reads bypass L1 (cp.async.cg / __ldcg).
__device__ __forceinline__ void grid_sync(u64 target) {
    __syncthreads();
    if (threadIdx.x == 0) {
        u64 old;
        asm volatile("atom.add.release.gpu.u64 %0, [%1], 1;"
                     : "=l"(old) : "l"(&g_arrive) : "memory");
        u64 v;
        do {
            asm volatile("ld.acquire.gpu.u64 %0, [%1];"
                         : "=l"(v) : "l"(&g_arrive) : "memory");
        } while (v < target);
    }
    __syncthreads();
}

// fast nonlinearities (MUFU-based; rel err ~1e-6)
__device__ __forceinline__ float fast_sigmoid(float x) {
    return __fdividef(1.f, 1.f + __expf(-x));
}
__device__ __forceinline__ float fast_tanh(float x) {
    return 1.f - __fdividef(2.f, 1.f + __expf(2.f * x));
}

// smem: 3 stages of 40 KB (Ah 16K | Al 16K | W 8K) + 40 KB scratch region
// (aliased: acc-reduction buffers during epilogue; s_hb during phase B).
#define STG    40960
#define OFF_AL 16384
#define OFF_W  32768
#define OFF_HB (3 * STG)
#define REDSTR 20           // floats per thread slot (80 B, conflict-free)
#define DYN_SMEM (3 * STG + 40960)

// ---------------------------------------------------------------------------
// prep (unchanged math): gate-interleave fp16 weights; split activations.
// ---------------------------------------------------------------------------
__global__ void prep_kernel(const float* __restrict__ Wih_f, const float* __restrict__ Whh_f,
                            const float* __restrict__ b_f,
                            const float* __restrict__ Wih_b, const float* __restrict__ Whh_b,
                            const float* __restrict__ b_b,
                            const float* __restrict__ dec) {
    int idx = blockIdx.x * blockDim.x + threadIdx.x;
    int stride = gridDim.x * blockDim.x;
    if (idx == 0) { g_arrive = 0ULL; g_xarrive = 0ULL; }

    for (int i = idx; i < 2 * G4 * KTOT; i += stride) {
        int dir = i / (G4 * KTOT);
        int rem = i - dir * (G4 * KTOT);
        int r = rem / KTOT, k = rem - r * KTOT;
        int orow = (r & 3) * HID + (r >> 2);
        float w;
        if (k < LATENT) w = (dir ? Wih_b : Wih_f)[orow * LATENT + k];
        else            w = (dir ? Whh_b : Whh_f)[orow * HID + (k - LATENT)];
        g_W[dir][r][k] = __float2half_rn(w);
    }
    for (int i = idx; i < 2 * G4; i += stride) {
        int dir = i / G4, r = i - dir * G4;
        g_bias[dir][r] = (dir ? b_b : b_f)[(r & 3) * HID + (r >> 2)];
    }
    for (int i = idx; i < 2 * 2 * BS * KTOT; i += stride) {
        int buf = i / (2 * BS * KTOT);
        int rem = i - buf * (2 * BS * KTOT);
        int dir = rem / (BS * KTOT);
        int rem2 = rem - dir * (BS * KTOT);
        int row = rem2 / KTOT, k = rem2 - row * KTOT;
        float v = (buf == 0 && k < LATENT) ? dec[row * LATENT + k] : 0.f;
        __half hi = __float2half_rn(v);
        __half lo = __float2half_rn(v - __half2float(hi));
        g_Ahi[buf][dir][row][k] = hi;
        g_Alo[buf][dir][row][k] = lo;
    }
    for (int i = idx; i < 2 * 2 * BS * HID; i += stride) ((float*)g_h)[i] = 0.f;
    for (int i = idx; i < 2 * BS * HID; i += stride)     ((float*)g_c)[i] = 0.f;
}

// ---------------------------------------------------------------------------
// persistent kernel: 128 blocks x 512 threads (16 warps), one launch, all T.
// phase A: block = (dir, 64 gate-cols); two 8-warp groups share the 4x2
//          32x32 warp-tile grid, K-split by kk (group 0: kk 0,1; group 1:
//          kk 2,3). Partial accs exchanged via padded smem, epilogue split
//          by mt. cp.async 3-stage ring, depth-1, as R13.
// phase B: head, 8-way K split over 512 threads; overlapped via g_xarrive.
// ---------------------------------------------------------------------------
__global__ void __launch_bounds__(NTHR, 1) lstm_persist(
        int T, float* __restrict__ out,
        const float* __restrict__ W_out, const float* __restrict__ b_out,
        const float* __restrict__ W_fc1, const float* __restrict__ b_fc1) {

    extern __shared__ __align__(16) unsigned char dsm[];
    const u32 smem_base = smem_u32(dsm);

    const int tid = threadIdx.x;
    const int bid = blockIdx.x;
    const int wid = tid >> 5;
    const int lane = tid & 31;
    const int g = wid >> 3;            // K-split group
    const int wg = wid & 7;            // warp within group

    const int dir = bid >> 6;
    const int colbase = (bid & 63) << 6;

    // warp tile mapping (shared by both groups): 4 along M, 2 along N
    const int wm = wg & 3;
    const int wn = wg >> 2;
    const int R0 = wm * 32;
    const int C0 = wn * 32;

    // ldmatrix per-lane constants
    const int arow = lane & 15;
    const u32 khA = (u32)(lane >> 4) * 16;
    const int brow = (lane & 7) + ((lane >> 4) & 1) * 8;
    const u32 khB = (u32)((lane >> 3) & 1) * 16;
    const u32 swA = (u32)(arow & 7) << 4;
    const u32 swB = (u32)(brow & 7) << 4;
    const u32 aRowOff0 = (u32)(R0 + arow) * 128;
    const u32 aRowOff1 = (u32)(R0 + 16 + arow) * 128;
    const u32 bRowOff0 = OFF_W + (u32)(C0 + brow) * 128;
    const u32 bRowOff1 = OFF_W + (u32)(C0 + 16 + brow) * 128;

    // cp.async per-thread precompute (512 threads): A hi/lo 1024 x 16B ->
    // 2 per thread; W 512 x 16B -> 1 per thread.
    u32 cpdstA[2], cpdstW;
    int cprowA[2], cpqA[2], cprowW, cpqW;
#pragma unroll
    for (int i = 0; i < 2; i++) {
        int p = tid + i * NTHR, row = p >> 3, q = p & 7;
        cprowA[i] = row; cpqA[i] = q;
        cpdstA[i] = SW128((u32)(row * 128 + q * 16));
    }
    {
        int row = tid >> 3, q = tid & 7;
        cprowW = row; cpqW = q;
        cpdstW = SW128((u32)(row * 128 + q * 16));
    }

    // head mapping
    const int bt = bid >> 3;   // 16 row-tiles of 8
    const int lt = bid & 7;    // 8 latent col-tiles of 64
    float* s_hb_f = (float*)(dsm + OFF_HB);          // phase-B staging
    float* redA = (float*)(dsm + OFF_HB);            // group0 -> group1 (mt=1)
    float* redB = redA + 256 * REDSTR;               // group1 -> group0 (mt=0)

    for (int t = 0; t < T; t++) {
        const int cur = t & 1;
        const int nxt = cur ^ 1;
        const __half* __restrict__ Ah = &g_Ahi[cur][dir][0][0];
        const __half* __restrict__ Al = &g_Alo[cur][dir][0][0];
        const __half* __restrict__ Wp = &g_W[dir][colbase][0];
        const u64 xtarget = (u64)t * NBLK;

#define ISSUE_CHUNK(cc, st)                                                   \
        {                                                                      \
            const u32 sb = smem_base + (u32)(st) * STG;                        \
            const size_t c64 = (size_t)(cc) * CHK;                             \
            _Pragma("unroll")                                                  \
            for (int i = 0; i < 2; i++) {                                      \
                const __half* s  = Ah + (size_t)cprowA[i] * KTOT + c64 + cpqA[i] * 8; \
                const __half* s2 = Al + (size_t)cprowA[i] * KTOT + c64 + cpqA[i] * 8; \
                CP16(sb + cpdstA[i], s);                                       \
                CP16(sb + OFF_AL + cpdstA[i], s2);                             \
            }                                                                  \
            {                                                                  \
                const __half* s = Wp + (size_t)cprowW * KTOT + c64 + cpqW * 8; \
                CP16(sb + OFF_W + cpdstW, s);                                  \
            }                                                                  \
            CP_COMMIT();                                                       \
        }

        // ================= phase A: K-split fp16 2-term HMMA ===============
        float acc[2][4][4];
#pragma unroll
        for (int mt = 0; mt < 2; mt++)
#pragma unroll
            for (int nt = 0; nt < 4; nt++)
#pragma unroll
                for (int i = 0; i < 4; i++) acc[mt][nt][i] = 0.f;

        ISSUE_CHUNK(MAPC(0), 0);

        int stage = 0;
#pragma unroll 1
        for (int c = 0; c < NCHUNK; c++) {
            if (c + 1 < NCHUNK) {
                if (c + 1 == 16) {
                    // first x-chunk: wait for all phase B(t-1)
                    if (tid == 0) {
                        u64 v;
                        do {
                            asm volatile("ld.acquire.gpu.u64 %0, [%1];"
                                         : "=l"(v) : "l"(&g_xarrive) : "memory");
                        } while (v < xtarget);
                    }
                    __syncthreads();
                }
                const int nstage = (stage == 2) ? 0 : stage + 1;
                ISSUE_CHUNK(MAPC(c + 1), nstage);
                CP_WAIT(1);
            } else {
                CP_WAIT(0);
            }
            __syncthreads();   // chunk c visible; ring period 3 protects reuse

            const u32 sb = smem_base + (u32)stage * STG;
            const u32 a0 = sb + aRowOff0, a1 = sb + aRowOff1;
            const u32 b0 = sb + bRowOff0, b1 = sb + bRowOff1;

#pragma unroll
            for (int kk2 = 0; kk2 < 2; kk2++) {
                const int kk = g * 2 + kk2;
                const u32 xA = ((u32)(kk * 32) + khA) ^ swA;
                const u32 xB = ((u32)(kk * 32) + khB) ^ swB;
                u32 ah[2][4], al[2][4], bw[2][4];
                LDSM4(ah[0], a0 + xA);
                LDSM4(ah[1], a1 + xA);
                LDSM4(al[0], a0 + OFF_AL + xA);
                LDSM4(al[1], a1 + OFF_AL + xA);
                LDSM4(bw[0], b0 + xB);
                LDSM4(bw[1], b1 + xB);
#pragma unroll
                for (int mt = 0; mt < 2; mt++)
#pragma unroll
                    for (int np = 0; np < 2; np++)
#pragma unroll
                        for (int hf = 0; hf < 2; hf++) {
                            const int nt = np * 2 + hf;
                            MMA16816(acc[mt][nt], ah[mt], bw[np][2 * hf], bw[np][2 * hf + 1]);
                            MMA16816(acc[mt][nt], al[mt], bw[np][2 * hf], bw[np][2 * hf + 1]);
                        }
            }
            stage = (stage == 2) ? 0 : stage + 1;
        }

        // -------- cross-group accumulator exchange (mt-halves) -------------
        {
            const int j = tid & 255;     // partner slot
            float* dst = (g == 0) ? redA : redB;
            const int mt_send = (g == 0) ? 1 : 0;
#pragma unroll
            for (int nt = 0; nt < 4; nt++)
                *(float4*)&dst[j * REDSTR + nt * 4] =
                    make_float4(acc[mt_send][nt][0], acc[mt_send][nt][1],
                                acc[mt_send][nt][2], acc[mt_send][nt][3]);
            __syncthreads();
            const float* src = (g == 0) ? redB : redA;
            const int mt_own = g;
#pragma unroll
            for (int nt = 0; nt < 4; nt++) {
                float4 v = *(const float4*)&src[j * REDSTR + nt * 4];
                acc[mt_own][nt][0] += v.x;
                acc[mt_own][nt][1] += v.y;
                acc[mt_own][nt][2] += v.z;
                acc[mt_own][nt][3] += v.w;
            }
        }

        // -------- epilogue: group g handles mt=g rows ----------------------
#pragma unroll
        for (int nt = 0; nt < 4; nt++) {
            float d0 = acc[g][nt][0], d1 = acc[g][nt][1];
            float d2 = acc[g][nt][2], d3 = acc[g][nt][3];
            float p0 = __shfl_xor_sync(0xffffffffu, d0, 1);
            float p1 = __shfl_xor_sync(0xffffffffu, d1, 1);
            float p2 = __shfl_xor_sync(0xffffffffu, d2, 1);
            float p3 = __shfl_xor_sync(0xffffffffu, d3, 1);
            if (!(lane & 1)) {
                const int q = (lane >> 1) & 1;
                const int col4 = colbase + C0 + nt * 8 + q * 4;
                const int jp = col4 >> 2;
                const float4 b4 = *(const float4*)&g_bias[dir][col4];
                const int r0 = R0 + g * 16 + (lane >> 2);
#pragma unroll
                for (int rr = 0; rr < 2; rr++) {
                    const int row = r0 + rr * 8;
                    float zi = (rr ? d2 : d0) + b4.x;
                    float zf = (rr ? d3 : d1) + b4.y;
                    float zg = (rr ? p2 : p0) + b4.z;
                    float zo = (rr ? p3 : p1) + b4.w;
                    float si = fast_sigmoid(zi);
                    float sf = fast_sigmoid(zf);
                    float so = fast_sigmoid(zo);
                    float c2 = sf * g_c[dir][row][jp] + si * fast_tanh(zg);
                    g_c[dir][row][jp] = c2;
                    float hv = so * fast_tanh(c2);
                    g_h[nxt][dir][row][jp] = hv;
                    __half hhi = __float2half_rn(hv);
                    __half hlo = __float2half_rn(hv - __half2float(hhi));
                    g_Ahi[nxt][dir][row][LATENT + jp] = hhi;
                    g_Alo[nxt][dir][row][LATENT + jp] = hlo;
                }
            }
        }

        grid_sync((u64)(t + 1) * NBLK);   // h(t) globally visible

        // ================= phase B: head (512 threads) =====================
        for (int i = tid; i < 8 * 256; i += NTHR) {
            int r = i >> 8;               // 0..7
            int k = (i & 255) * 4;        // 0..1020
            float4 v = __ldcg((const float4*)&g_h[nxt][1][bt * 8 + r][k]);
            *(float4*)&s_hb_f[r * ROWF + (k >> 7) * SEGF + (k & 127)] = v;
        }
        __syncthreads();

        // x_next = hb @ W_out^T + b_out; 8-way K split per latent column
        {
            const int l_loc = tid >> 3;   // 0..63
            const int q = tid & 7;        // 0..7
            const int l = lt * 64 + l_loc;
            const ulonglong2* __restrict__ wp2 =
                (const ulonglong2*)(W_out + (size_t)l * HID) + q * 32;
            const u64* __restrict__ hp = (const u64*)s_hb_f + q * (SEGF / 2);
            u64 hacc[8];
#pragma unroll
            for (int r = 0; r < 8; r++) hacc[r] = 0ull;
#pragma unroll 2
            for (int k4 = 0; k4 < 32; k4++) {
                ulonglong2 ww = wp2[k4];
#pragma unroll
                for (int r = 0; r < 8; r++) {
                    fma2(hacc[r], ww.x, hp[r * (ROWF / 2) + 2 * k4]);
                    fma2(hacc[r], ww.y, hp[r * (ROWF / 2) + 2 * k4 + 1]);
                }
            }
#pragma unroll
            for (int r = 0; r < 8; r++) {
                float lo, hi; unpack2(hacc[r], lo, hi);
                float s = lo + hi;
                s += __shfl_xor_sync(0xffffffffu, s, 1);
                s += __shfl_xor_sync(0xffffffffu, s, 2);
                s += __shfl_xor_sync(0xffffffffu, s, 4);
                if (q == 0) {
                    float xv = s + b_out[l];
                    int row = bt * 8 + r;
                    __half xh = __float2half_rn(xv);
                    __half xl = __float2half_rn(xv - __half2float(xh));
                    g_Ahi[nxt][0][row][l] = xh;
                    g_Ahi[nxt][1][row][l] = xh;
                    g_Alo[nxt][0][row][l] = xl;
                    g_Alo[nxt][1][row][l] = xl;
                }
            }
        }

        // out[b, t] = relu(concat(hf,hb)) . W_fc1 + b_fc1   (lt==0 blocks)
        if (lt == 0 && tid < 256) {
            const int r = tid >> 5, ln = tid & 31;
            const int b = bt * 8 + r;
            const float* __restrict__ hf = &g_h[nxt][0][b][0];
            float facc = 0.f;
            for (int k = ln * 4; k < HID; k += 128) {
                float4 f   = __ldcg((const float4*)&hf[k]);
                float4 wf  = *(const float4*)&W_fc1[k];
                float4 hb4 = *(const float4*)&s_hb_f[r * ROWF + (k >> 7) * SEGF + (k & 127)];
                float4 wb  = *(const float4*)&W_fc1[HID + k];
                facc += fmaxf(f.x, 0.f) * wf.x + fmaxf(f.y, 0.f) * wf.y
                      + fmaxf(f.z, 0.f) * wf.z + fmaxf(f.w, 0.f) * wf.w
                      + fmaxf(hb4.x, 0.f) * wb.x + fmaxf(hb4.y, 0.f) * wb.y
                      + fmaxf(hb4.z, 0.f) * wb.z + fmaxf(hb4.w, 0.f) * wb.w;
            }
#pragma unroll
            for (int off = 16; off; off >>= 1)
                facc += __shfl_xor_sync(0xffffffffu, facc, off);
            if (ln == 0) out[(size_t)b * T + t] = facc + b_fc1[0];
        }

        // block-local completion of phase B (s_hb reads done before next
        // step's reduction/staging overwrites dsm); then announce x(t+1).
        __syncthreads();
        if (tid == 0) {
            u64 old;
            asm volatile("atom.add.release.gpu.u64 %0, [%1], 1;"
                         : "=l"(old) : "l"(&g_xarrive) : "memory");
        }
    }
}

// ---------------------------------------------------------------------------
extern "C" void kernel_launch(void* const* d_in, const int* in_sizes, int n_in,
                              void* d_out, int out_size) {
    const float* dec   = (const float*)d_in[0];
    // d_in[1] = lengths (T derives from out_size)
    const float* Wih_f = (const float*)d_in[2];
    const float* Whh_f = (const float*)d_in[3];
    const float* b_f   = (const float*)d_in[4];
    const float* Wih_b = (const float*)d_in[5];
    const float* Whh_b = (const float*)d_in[6];
    const float* b_b   = (const float*)d_in[7];
    const float* W_out = (const float*)d_in[8];
    const float* b_out = (const float*)d_in[9];
    const float* W_fc1 = (const float*)d_in[10];
    const float* b_fc1 = (const float*)d_in[11];
    float* out = (float*)d_out;

    const int T = out_size / BS;

    cudaFuncSetAttribute(lstm_persist, cudaFuncAttributeMaxDynamicSharedMemorySize, DYN_SMEM);

    prep_kernel<<<1024, 256>>>(Wih_f, Whh_f, b_f, Wih_b, Whh_b, b_b, dec);
    if (T > 0) {
        lstm_persist<<<NBLK, NTHR, DYN_SMEM>>>(T, out, W_out, b_out, W_fc1, b_fc1);
    }
}